// round 4
// baseline (speedup 1.0000x reference)
#include <cuda_runtime.h>
#include <cstdint>

// ---------------- fixed problem dims ----------------
#define S_SITES   1024
#define APS       2
#define A_ALLELES (S_SITES * APS)      // 2048
#define RPA0      20
#define RPA1      10
#define R0_MAX    (A_ALLELES * RPA0)   // 40960
#define R1_MAX    (A_ALLELES * RPA1)   // 20480
#define CIN       10
#define LEN       100
#define FF        32
#define KK        5
#define HH        64
#define NEXP      3
#define LOUT      96
#define WCOUNT    (CIN * KK)            // 50

// ---------------- scratch ----------------
__device__ float g_feat0[R0_MAX * FF];
__device__ float g_feat1[R1_MAX * FF];
__device__ float g_al0[A_ALLELES * FF];
__device__ float g_al1[A_ALLELES * FF];

// ============================================================
// Stage A: persistent tf32 tensor-core conv, cp.async pipeline,
// weights staged in shared (pre-converted tf32), 2 blocks/SM.
// ============================================================
#define RPB    4
#define SROW   104

__device__ __forceinline__ uint32_t f2tf32(float f) {
    uint32_t r;
    asm("cvt.rna.tf32.f32 %0, %1;" : "=r"(r) : "f"(f));
    return r;
}

__device__ __forceinline__ void mma_tf32(float acc[4],
                                         uint32_t a0, uint32_t a1, uint32_t a2, uint32_t a3,
                                         uint32_t b0, uint32_t b1) {
    asm volatile(
        "mma.sync.aligned.m16n8k8.row.col.f32.tf32.tf32.f32 "
        "{%0,%1,%2,%3}, {%4,%5,%6,%7}, {%8,%9}, {%0,%1,%2,%3};"
        : "+f"(acc[0]), "+f"(acc[1]), "+f"(acc[2]), "+f"(acc[3])
        : "r"(a0), "r"(a1), "r"(a2), "r"(a3), "r"(b0), "r"(b1));
}

__device__ __forceinline__ void cp_async16(void* smem, const void* gmem) {
    uint32_t s = (uint32_t)__cvta_generic_to_shared(smem);
    asm volatile("cp.async.cg.shared.global [%0], [%1], 16;" :: "r"(s), "l"(gmem));
}
#define CP_COMMIT()   asm volatile("cp.async.commit_group;")
#define CP_WAIT(N)    asm volatile("cp.async.wait_group %0;" :: "n"(N))

// shared weight bank layout: sw[tech][kt][h][(nt*8+lg)*4 + li]
//   value = tf32( w[(nt*8+lg)*WCOUNT + kt*8 + h*4 + li] ), 0 if kk >= 50
#define SW_IDX(tech, kt, h, e)  ((((tech) * 7 + (kt)) * 2 + (h)) * 128 + (e))

__global__ __launch_bounds__(256, 2)
void conv_persist_kernel(const float* __restrict__ x0,
                         const float* __restrict__ w0,
                         const float* __restrict__ b0,
                         const float* __restrict__ x1,
                         const float* __restrict__ w1,
                         const float* __restrict__ b1,
                         int T0, int T, int chunk)
{
    __shared__ float    sx[2][RPB][CIN * SROW];   // 33280 B
    __shared__ uint32_t sw[2 * 7 * 2 * 128];      // 14336 B
    __shared__ float    sb[2][FF];                //   256 B
    __shared__ float    sred[RPB][2][FF];         //  1024 B

    const int tid  = threadIdx.x;
    const int warp = tid >> 5;
    const int lane = tid & 31;
    const int li   = lane & 3;
    const int lg   = lane >> 2;

    // ---- one-time: convert weights for both techs into shared ----
    for (int i = tid; i < 2 * 7 * 2 * 128; i += 256) {
        const int e    = i & 127;
        const int rest = i >> 7;
        const int h    = rest & 1;
        const int kt   = (rest >> 1) % 7;
        const int tech = rest / 14;
        const int f    = e >> 2;           // nt*8+lg
        const int eli  = e & 3;
        const int kk   = kt * 8 + h * 4 + eli;
        const float* w = tech ? w1 : w0;
        sw[i] = (kk < WCOUNT) ? f2tf32(w[f * WCOUNT + kk]) : 0u;
    }
    if (tid < 2 * FF) {
        const int tech = tid >> 5;
        const int f    = tid & 31;
        sb[tech][f] = tech ? b1[f] : b0[f];
    }

    const int tbeg = blockIdx.x * chunk;
    if (tbeg >= T) { return; }
    const int n = min(chunk, T - tbeg);

    auto prefetch = [&](int t, int st) {
        const bool is0 = (t < T0);
        const float* xx = is0 ? x0 : x1;
        const int rbase = is0 ? t * RPB : (t - T0) * RPB;
        const float4* gx = (const float4*)(xx + (size_t)rbase * (CIN * LEN));
        for (int idx = tid; idx < RPB * 250; idx += 256) {
            const int r   = idx / 250;
            const int rem = idx - r * 250;
            const int c   = rem / 25;
            const int i   = rem - c * 25;
            cp_async16(&sx[st][r][c * SROW + i * 4], &gx[(size_t)r * 250 + rem]);
        }
    };

    // ---- prologue ----
    prefetch(tbeg, 0); CP_COMMIT();
    if (n > 1) { prefetch(tbeg + 1, 1); CP_COMMIT(); CP_WAIT(1); }
    else       { CP_WAIT(0); }
    __syncthreads();   // also covers sw/sb fill

    const int rloc = warp >> 1;
    const int half = warp & 1;
    const int rowb = half * 48 + lg;

    for (int it = 0; it < n; it++) {
        const int t    = tbeg + it;
        const int st   = it & 1;
        const bool is0 = (t < T0);
        const int tech = is0 ? 0 : 1;

        const float* __restrict__ sr = sx[st][rloc];

        float acc[3][4][4];
#pragma unroll
        for (int mt = 0; mt < 3; mt++)
#pragma unroll
            for (int nt = 0; nt < 4; nt++)
#pragma unroll
                for (int j = 0; j < 4; j++) acc[mt][nt][j] = 0.0f;

#pragma unroll 1
        for (int kt = 0; kt < 7; kt++) {
            // im2col offsets for this kt (clamped; padded weights are 0)
            const int kk0 = kt * 8 + li;
            const int kk1 = kk0 + 4;
            const int ka0 = (kk0 < WCOUNT) ? kk0 : (WCOUNT - 1);
            const int ka1 = (kk1 < WCOUNT) ? kk1 : (WCOUNT - 1);
            const int o0  = (ka0 / KK) * SROW + (ka0 % KK);
            const int o1  = (ka1 / KK) * SROW + (ka1 % KK);

            // B fragments from shared: 8 conflict-free LDS
            uint32_t Bf[4][2];
            const uint32_t* swp0 = &sw[SW_IDX(tech, kt, 0, lg * 4 + li)];
            const uint32_t* swp1 = &sw[SW_IDX(tech, kt, 1, lg * 4 + li)];
#pragma unroll
            for (int nt = 0; nt < 4; nt++) {
                Bf[nt][0] = swp0[nt * 32];
                Bf[nt][1] = swp1[nt * 32];
            }

#pragma unroll
            for (int mt = 0; mt < 3; mt++) {
                const int row = rowb + mt * 16;
                const uint32_t a0 = __float_as_uint(sr[o0 + row]);
                const uint32_t a1 = __float_as_uint(sr[o0 + row + 8]);
                const uint32_t a2 = __float_as_uint(sr[o1 + row]);
                const uint32_t a3 = __float_as_uint(sr[o1 + row + 8]);
#pragma unroll
                for (int nt = 0; nt < 4; nt++)
                    mma_tf32(acc[mt][nt], a0, a1, a2, a3, Bf[nt][0], Bf[nt][1]);
            }
        }

        // ---- epilogue: bias + relu + row-sum, lane reduce ----
#pragma unroll
        for (int nt = 0; nt < 4; nt++) {
            const float bbl0 = sb[tech][nt * 8 + 2 * li + 0];
            const float bbl1 = sb[tech][nt * 8 + 2 * li + 1];
            float s0 = 0.0f, s1 = 0.0f;
#pragma unroll
            for (int mt = 0; mt < 3; mt++) {
                s0 += fmaxf(acc[mt][nt][0] + bbl0, 0.0f);
                s0 += fmaxf(acc[mt][nt][2] + bbl0, 0.0f);
                s1 += fmaxf(acc[mt][nt][1] + bbl1, 0.0f);
                s1 += fmaxf(acc[mt][nt][3] + bbl1, 0.0f);
            }
#pragma unroll
            for (int o = 16; o >= 4; o >>= 1) {
                s0 += __shfl_down_sync(0xffffffffu, s0, o);
                s1 += __shfl_down_sync(0xffffffffu, s1, o);
            }
            if (lane < 4) {
                sred[rloc][half][nt * 8 + 2 * lane + 0] = s0;
                sred[rloc][half][nt * 8 + 2 * lane + 1] = s1;
            }
        }

        __syncthreads();   // sred complete; sx[st] free

        if (tid < RPB * FF) {
            const int r = tid >> 5;
            const int f = tid & 31;
            const int rbase = is0 ? t * RPB : (t - T0) * RPB;
            float* feat = is0 ? g_feat1 : g_feat0;
            feat = is0 ? g_feat0 : g_feat1;
            feat[(size_t)(rbase + r) * FF + f] =
                (sred[r][0][f] + sred[r][1][f]) * (1.0f / (float)LOUT);
        }

        if (it + 2 < n) {
            prefetch(tbeg + it + 2, st);
            CP_COMMIT();
            CP_WAIT(1);
        } else {
            CP_WAIT(0);
        }
        __syncthreads();
    }
}

// ============================================================
// Stage B: allele segment sums, both techs, one launch.
// ============================================================
__global__ void allele_sum_all_kernel()
{
    const int idx = blockIdx.x * blockDim.x + threadIdx.x;
    const int half = A_ALLELES * FF;
    if (idx >= 2 * half) return;
    const int which = idx >= half;
    const int j = which ? idx - half : idx;
    const int a = j >> 5;
    const int f = j & 31;

    const float* feat = which ? g_feat1 : g_feat0;
    float*       al   = which ? g_al1  : g_al0;
    const int    rpa  = which ? RPA1   : RPA0;

    const float* p = feat + (size_t)a * rpa * FF + f;
    float s = 0.0f;
#pragma unroll 4
    for (int i = 0; i < rpa; i++) s += p[(size_t)i * FF];
    al[j] = s;
}

// ============================================================
// Fused tail: warp per site.
// ============================================================
__device__ __forceinline__ float mlp32(float in, const float* __restrict__ w1,
                                       const float* __restrict__ b1,
                                       const float* __restrict__ w2, float b2,
                                       int lane)
{
    float h0 = b1[lane], h1 = b1[lane + 32];
#pragma unroll
    for (int f = 0; f < FF; f++) {
        const float v = __shfl_sync(0xffffffffu, in, f);
        h0 = fmaf(v, w1[f * HH + lane], h0);
        h1 = fmaf(v, w1[f * HH + lane + 32], h1);
    }
    float p = fmaxf(h0, 0.0f) * w2[lane] + fmaxf(h1, 0.0f) * w2[lane + 32];
#pragma unroll
    for (int o = 16; o > 0; o >>= 1) p += __shfl_xor_sync(0xffffffffu, p, o);
    return p + b2;
}

__device__ __forceinline__ float mlp64(float in0, float in1,
                                       const float* __restrict__ w1,
                                       const float* __restrict__ b1,
                                       const float* __restrict__ w2, float b2,
                                       int lane)
{
    float h0 = b1[lane], h1 = b1[lane + 32];
#pragma unroll
    for (int f = 0; f < FF; f++) {
        const float v0 = __shfl_sync(0xffffffffu, in0, f);
        const float v1 = __shfl_sync(0xffffffffu, in1, f);
        h0 = fmaf(v0, w1[f * HH + lane], h0);
        h1 = fmaf(v0, w1[f * HH + lane + 32], h1);
        h0 = fmaf(v1, w1[(FF + f) * HH + lane], h0);
        h1 = fmaf(v1, w1[(FF + f) * HH + lane + 32], h1);
    }
    float p = fmaxf(h0, 0.0f) * w2[lane] + fmaxf(h1, 0.0f) * w2[lane + 32];
#pragma unroll
    for (int o = 16; o > 0; o >>= 1) p += __shfl_xor_sync(0xffffffffu, p, o);
    return p + b2;
}

__global__ __launch_bounds__(256)
void tail_kernel(const float* __restrict__ mw,   const float* __restrict__ mb,
                 const float* __restrict__ ngs_w1, const float* __restrict__ ngs_b1,
                 const float* __restrict__ ngs_w2, const float* __restrict__ ngs_b2,
                 const float* __restrict__ tgs_w1, const float* __restrict__ tgs_b1,
                 const float* __restrict__ tgs_w2, const float* __restrict__ tgs_b2,
                 const float* __restrict__ hyb_w1, const float* __restrict__ hyb_b1,
                 const float* __restrict__ hyb_w2, const float* __restrict__ hyb_b2,
                 float* __restrict__ out)
{
    const int warp = threadIdx.x >> 5;
    const int lane = threadIdx.x & 31;
    const int s = blockIdx.x * (blockDim.x >> 5) + warp;
    if (s >= S_SITES) return;

    const float a00 = g_al0[(2 * s)     * FF + lane];
    const float a01 = g_al0[(2 * s + 1) * FF + lane];
    const float a10 = g_al1[(2 * s)     * FF + lane];
    const float a11 = g_al1[(2 * s + 1) * FF + lane];

    const float v0 = a00 + a01;
    const float v1 = a10 + a11;
    float l[NEXP];
#pragma unroll
    for (int e = 0; e < NEXP; e++) {
        float p = v0 * mw[lane * NEXP + e] + v1 * mw[(FF + lane) * NEXP + e];
#pragma unroll
        for (int o = 16; o > 0; o >>= 1) p += __shfl_xor_sync(0xffffffffu, p, o);
        l[e] = p + mb[e];
    }

    const float ngs_b2v = ngs_b2[0], tgs_b2v = tgs_b2[0], hyb_b2v = hyb_b2[0];
    const float ln0 = mlp32(a00, ngs_w1, ngs_b1, ngs_w2, ngs_b2v, lane);
    const float ln1 = mlp32(a01, ngs_w1, ngs_b1, ngs_w2, ngs_b2v, lane);
    const float lt0 = mlp32(a10, tgs_w1, tgs_b1, tgs_w2, tgs_b2v, lane);
    const float lt1 = mlp32(a11, tgs_w1, tgs_b1, tgs_w2, tgs_b2v, lane);
    const float lh0 = mlp64(a00, a10, hyb_w1, hyb_b1, hyb_w2, hyb_b2v, lane);
    const float lh1 = mlp64(a01, a11, hyb_w1, hyb_b1, hyb_w2, hyb_b2v, lane);

    if (lane == 0) {
        float pe[3][2] = {{ln0, ln1}, {lt0, lt1}, {lh0, lh1}};
#pragma unroll
        for (int e = 0; e < 3; e++) {
            const float m  = fmaxf(pe[e][0], pe[e][1]);
            const float z0 = expf(pe[e][0] - m);
            const float z1 = expf(pe[e][1] - m);
            const float inv = 1.0f / (z0 + z1);
            out[e * A_ALLELES + 2 * s]     = z0 * inv;
            out[e * A_ALLELES + 2 * s + 1] = z1 * inv;
        }
        const float m = fmaxf(l[0], fmaxf(l[1], l[2]));
        const float z0 = expf(l[0] - m), z1 = expf(l[1] - m), z2 = expf(l[2] - m);
        const float inv = 1.0f / (z0 + z1 + z2);
        out[3 * A_ALLELES + s * NEXP + 0] = z0 * inv;
        out[3 * A_ALLELES + s * NEXP + 1] = z1 * inv;
        out[3 * A_ALLELES + s * NEXP + 2] = z2 * inv;
    }
}

// ============================================================
// launch
// ============================================================
extern "C" void kernel_launch(void* const* d_in, const int* in_sizes, int n_in,
                              void* d_out, int out_size)
{
    const float* tensors0 = (const float*)d_in[0];
    const float* tensors1 = (const float*)d_in[1];
    const float* conv0_w  = (const float*)d_in[2];
    const float* conv0_b  = (const float*)d_in[3];
    const float* conv1_w  = (const float*)d_in[4];
    const float* conv1_b  = (const float*)d_in[5];
    const float* meta_w   = (const float*)d_in[6];
    const float* meta_b   = (const float*)d_in[7];
    const float* ngs_w1   = (const float*)d_in[8];
    const float* ngs_b1   = (const float*)d_in[9];
    const float* ngs_w2   = (const float*)d_in[10];
    const float* ngs_b2   = (const float*)d_in[11];
    const float* tgs_w1   = (const float*)d_in[12];
    const float* tgs_b1   = (const float*)d_in[13];
    const float* tgs_w2   = (const float*)d_in[14];
    const float* tgs_b2   = (const float*)d_in[15];
    const float* hyb_w1   = (const float*)d_in[16];
    const float* hyb_b1   = (const float*)d_in[17];
    const float* hyb_w2   = (const float*)d_in[18];
    const float* hyb_b2   = (const float*)d_in[19];

    float* out = (float*)d_out;

    const int R0 = in_sizes[0] / (CIN * LEN);
    const int R1 = in_sizes[1] / (CIN * LEN);
    const int T0 = R0 / RPB;
    const int T  = T0 + R1 / RPB;

    const int GRID  = 296;                       // 2 blocks per SM
    const int chunk = (T + GRID - 1) / GRID;

    conv_persist_kernel<<<GRID, 256>>>(tensors0, conv0_w, conv0_b,
                                       tensors1, conv1_w, conv1_b,
                                       T0, T, chunk);

    allele_sum_all_kernel<<<(2 * A_ALLELES * FF + 255) / 256, 256>>>();

    tail_kernel<<<(S_SITES + 7) / 8, 256>>>(
        meta_w, meta_b,
        ngs_w1, ngs_b1, ngs_w2, ngs_b2,
        tgs_w1, tgs_b1, tgs_w2, tgs_b2,
        hyb_w1, hyb_b1, hyb_w2, hyb_b2,
        out);
}

// round 5
// speedup vs baseline: 1.0896x; 1.0896x over previous
#include <cuda_runtime.h>
#include <cstdint>

// ---------------- fixed problem dims ----------------
#define S_SITES   1024
#define APS       2
#define A_ALLELES (S_SITES * APS)      // 2048
#define RPA0      20
#define RPA1      10
#define R0_MAX    (A_ALLELES * RPA0)   // 40960
#define R1_MAX    (A_ALLELES * RPA1)   // 20480
#define CIN       10
#define LEN       100
#define FF        32
#define KK        5
#define HH        64
#define NEXP      3
#define LOUT      96
#define WCOUNT    (CIN * KK)            // 50

// ---------------- scratch ----------------
__device__ float g_feat0[R0_MAX * FF];
__device__ float g_feat1[R1_MAX * FF];

// ============================================================
// Stage A: persistent tf32 tensor-core conv, cp.async pipeline,
// B in registers, 2 blocks/SM.
// ============================================================
#define RPB    4
#define SROW   104

__device__ __forceinline__ uint32_t f2tf32(float f) {
    uint32_t r;
    asm("cvt.rna.tf32.f32 %0, %1;" : "=r"(r) : "f"(f));
    return r;
}

__device__ __forceinline__ void mma_tf32(float acc[4],
                                         uint32_t a0, uint32_t a1, uint32_t a2, uint32_t a3,
                                         uint32_t b0, uint32_t b1) {
    asm volatile(
        "mma.sync.aligned.m16n8k8.row.col.f32.tf32.tf32.f32 "
        "{%0,%1,%2,%3}, {%4,%5,%6,%7}, {%8,%9}, {%0,%1,%2,%3};"
        : "+f"(acc[0]), "+f"(acc[1]), "+f"(acc[2]), "+f"(acc[3])
        : "r"(a0), "r"(a1), "r"(a2), "r"(a3), "r"(b0), "r"(b1));
}

__device__ __forceinline__ void cp_async16(void* smem, const void* gmem) {
    uint32_t s = (uint32_t)__cvta_generic_to_shared(smem);
    asm volatile("cp.async.cg.shared.global [%0], [%1], 16;" :: "r"(s), "l"(gmem));
}
#define CP_COMMIT()   asm volatile("cp.async.commit_group;")
#define CP_WAIT(N)    asm volatile("cp.async.wait_group %0;" :: "n"(N))

__global__ __launch_bounds__(256, 2)
void conv_persist_kernel(const float* __restrict__ x0,
                         const float* __restrict__ w0,
                         const float* __restrict__ b0,
                         const float* __restrict__ x1,
                         const float* __restrict__ w1,
                         const float* __restrict__ b1,
                         int T0, int T, int chunk)
{
    __shared__ float sx[2][RPB][CIN * SROW];   // 33280 B
    __shared__ float sb[2][FF];                //   256 B
    __shared__ float sred[RPB][2][FF];         //  1024 B

    const int tid  = threadIdx.x;
    const int warp = tid >> 5;
    const int lane = tid & 31;
    const int li   = lane & 3;
    const int lg   = lane >> 2;

    // ---- biases into shared once ----
    if (tid < 2 * FF) {
        const int tech = tid >> 5;
        const int f    = tid & 31;
        sb[tech][f] = tech ? b1[f] : b0[f];
    }

    const int tbeg = blockIdx.x * chunk;
    if (tbeg >= T) return;
    const int n = min(chunk, T - tbeg);

    // ---- im2col offsets, packed (off0 | off1<<16) per kt ----
    uint32_t offp[7];
#pragma unroll
    for (int kt = 0; kt < 7; kt++) {
        const int kk0 = kt * 8 + li;
        const int kk1 = kk0 + 4;
        const int ka0 = (kk0 < WCOUNT) ? kk0 : (WCOUNT - 1);
        const int ka1 = (kk1 < WCOUNT) ? kk1 : (WCOUNT - 1);
        const uint32_t o0 = (uint32_t)((ka0 / KK) * SROW + (ka0 % KK));
        const uint32_t o1 = (uint32_t)((ka1 / KK) * SROW + (ka1 % KK));
        offp[kt] = o0 | (o1 << 16);
    }

    // ---- prefetch index precompute (hoists divisions) ----
    // dst float offset = idx*4 + pad, pad = (idx/250)*40 + ((idx%250)/25)*4
    int ppad[4];
#pragma unroll
    for (int j = 0; j < 4; j++) {
        const int idx = tid + j * 256;
        const int r   = idx / 250;
        const int rem = idx - r * 250;
        const int c   = rem / 25;
        ppad[j] = r * 40 + c * 4;
    }

    auto prefetch = [&](int t, int st) {
        const bool is0 = (t < T0);
        const float* xx = is0 ? x0 : x1;
        const int rbase = is0 ? t * RPB : (t - T0) * RPB;
        const float* gp = xx + (size_t)rbase * (CIN * LEN);
        float* sp = &sx[st][0][0];
#pragma unroll
        for (int j = 0; j < 4; j++) {
            const int idx = tid + j * 256;
            if (idx < RPB * 250)
                cp_async16(sp + idx * 4 + ppad[j], gp + idx * 4);
        }
    };

    // ---- per-tech B fragments in registers (zero-padded beyond 50) ----
    uint32_t B[7][4][2];
    int curtech = -1;

    // ---- prologue ----
    prefetch(tbeg, 0); CP_COMMIT();
    if (n > 1) { prefetch(tbeg + 1, 1); CP_COMMIT(); CP_WAIT(1); }
    else       { CP_WAIT(0); }
    __syncthreads();   // also covers sb fill

    const int rloc = warp >> 1;
    const int half = warp & 1;
    const int rowb = half * 48 + lg;

    for (int it = 0; it < n; it++) {
        const int t    = tbeg + it;
        const int st   = it & 1;
        const bool is0 = (t < T0);
        const int tech = is0 ? 0 : 1;

        if (tech != curtech) {
            curtech = tech;
            const float* w = is0 ? w0 : w1;
#pragma unroll
            for (int kt = 0; kt < 7; kt++) {
                const int kk0 = kt * 8 + li;
                const int kk1 = kk0 + 4;
#pragma unroll
                for (int nt = 0; nt < 4; nt++) {
                    const int f = nt * 8 + lg;
                    B[kt][nt][0] = (kk0 < WCOUNT) ? f2tf32(w[f * WCOUNT + kk0]) : 0u;
                    B[kt][nt][1] = (kk1 < WCOUNT) ? f2tf32(w[f * WCOUNT + kk1]) : 0u;
                }
            }
        }

        const float* __restrict__ sr = sx[st][rloc];

        float acc[3][4][4];
#pragma unroll
        for (int mt = 0; mt < 3; mt++)
#pragma unroll
            for (int nt = 0; nt < 4; nt++)
#pragma unroll
                for (int j = 0; j < 4; j++) acc[mt][nt][j] = 0.0f;

#pragma unroll
        for (int kt = 0; kt < 7; kt++) {
            const int o0 = (int)(offp[kt] & 0xFFFFu);
            const int o1 = (int)(offp[kt] >> 16);
#pragma unroll
            for (int mt = 0; mt < 3; mt++) {
                const int row = rowb + mt * 16;
                const uint32_t a0 = __float_as_uint(sr[o0 + row]);
                const uint32_t a1 = __float_as_uint(sr[o0 + row + 8]);
                const uint32_t a2 = __float_as_uint(sr[o1 + row]);
                const uint32_t a3 = __float_as_uint(sr[o1 + row + 8]);
#pragma unroll
                for (int nt = 0; nt < 4; nt++)
                    mma_tf32(acc[mt][nt], a0, a1, a2, a3, B[kt][nt][0], B[kt][nt][1]);
            }
        }

        // ---- epilogue: bias + relu + row-sum, lane reduce ----
#pragma unroll
        for (int nt = 0; nt < 4; nt++) {
            const float bbl0 = sb[tech][nt * 8 + 2 * li + 0];
            const float bbl1 = sb[tech][nt * 8 + 2 * li + 1];
            float s0 = 0.0f, s1 = 0.0f;
#pragma unroll
            for (int mt = 0; mt < 3; mt++) {
                s0 += fmaxf(acc[mt][nt][0] + bbl0, 0.0f);
                s0 += fmaxf(acc[mt][nt][2] + bbl0, 0.0f);
                s1 += fmaxf(acc[mt][nt][1] + bbl1, 0.0f);
                s1 += fmaxf(acc[mt][nt][3] + bbl1, 0.0f);
            }
#pragma unroll
            for (int o = 16; o >= 4; o >>= 1) {
                s0 += __shfl_down_sync(0xffffffffu, s0, o);
                s1 += __shfl_down_sync(0xffffffffu, s1, o);
            }
            if (lane < 4) {
                sred[rloc][half][nt * 8 + 2 * lane + 0] = s0;
                sred[rloc][half][nt * 8 + 2 * lane + 1] = s1;
            }
        }

        __syncthreads();   // sred complete; sx[st] free

        if (tid < RPB * FF) {
            const int r = tid >> 5;
            const int f = tid & 31;
            const int rbase = is0 ? t * RPB : (t - T0) * RPB;
            float* feat = is0 ? g_feat0 : g_feat1;
            feat[(size_t)(rbase + r) * FF + f] =
                (sred[r][0][f] + sred[r][1][f]) * (1.0f / (float)LOUT);
        }

        if (it + 2 < n) {
            prefetch(tbeg + it + 2, st);
            CP_COMMIT();
            CP_WAIT(1);
        } else {
            CP_WAIT(0);
        }
        __syncthreads();
    }
}

// ============================================================
// Fused tail: warp per site. Allele sums directly from feat,
// meta gate + 3 experts x 2 alleles + softmaxes. One launch.
// ============================================================
__device__ __forceinline__ float mlp32(float in, const float* __restrict__ w1,
                                       const float* __restrict__ b1,
                                       const float* __restrict__ w2, float b2,
                                       int lane)
{
    float h0 = b1[lane], h1 = b1[lane + 32];
#pragma unroll
    for (int f = 0; f < FF; f++) {
        const float v = __shfl_sync(0xffffffffu, in, f);
        h0 = fmaf(v, w1[f * HH + lane], h0);
        h1 = fmaf(v, w1[f * HH + lane + 32], h1);
    }
    float p = fmaxf(h0, 0.0f) * w2[lane] + fmaxf(h1, 0.0f) * w2[lane + 32];
#pragma unroll
    for (int o = 16; o > 0; o >>= 1) p += __shfl_xor_sync(0xffffffffu, p, o);
    return p + b2;
}

__device__ __forceinline__ float mlp64(float in0, float in1,
                                       const float* __restrict__ w1,
                                       const float* __restrict__ b1,
                                       const float* __restrict__ w2, float b2,
                                       int lane)
{
    float h0 = b1[lane], h1 = b1[lane + 32];
#pragma unroll
    for (int f = 0; f < FF; f++) {
        const float v0 = __shfl_sync(0xffffffffu, in0, f);
        const float v1 = __shfl_sync(0xffffffffu, in1, f);
        h0 = fmaf(v0, w1[f * HH + lane], h0);
        h1 = fmaf(v0, w1[f * HH + lane + 32], h1);
        h0 = fmaf(v1, w1[(FF + f) * HH + lane], h0);
        h1 = fmaf(v1, w1[(FF + f) * HH + lane + 32], h1);
    }
    float p = fmaxf(h0, 0.0f) * w2[lane] + fmaxf(h1, 0.0f) * w2[lane + 32];
#pragma unroll
    for (int o = 16; o > 0; o >>= 1) p += __shfl_xor_sync(0xffffffffu, p, o);
    return p + b2;
}

__global__ __launch_bounds__(256)
void tail_kernel(const float* __restrict__ mw,   const float* __restrict__ mb,
                 const float* __restrict__ ngs_w1, const float* __restrict__ ngs_b1,
                 const float* __restrict__ ngs_w2, const float* __restrict__ ngs_b2,
                 const float* __restrict__ tgs_w1, const float* __restrict__ tgs_b1,
                 const float* __restrict__ tgs_w2, const float* __restrict__ tgs_b2,
                 const float* __restrict__ hyb_w1, const float* __restrict__ hyb_b1,
                 const float* __restrict__ hyb_w2, const float* __restrict__ hyb_b2,
                 float* __restrict__ out)
{
    const int warp = threadIdx.x >> 5;
    const int lane = threadIdx.x & 31;
    const int s = blockIdx.x * (blockDim.x >> 5) + warp;
    if (s >= S_SITES) return;

    // ---- allele segment sums directly from feat (contiguous reads) ----
    float a00 = 0.0f, a01 = 0.0f, a10 = 0.0f, a11 = 0.0f;
    {
        const float* p0 = g_feat0 + (size_t)(2 * s) * RPA0 * FF + lane;
#pragma unroll 4
        for (int i = 0; i < RPA0; i++) a00 += p0[(size_t)i * FF];
#pragma unroll 4
        for (int i = 0; i < RPA0; i++) a01 += p0[(size_t)(RPA0 + i) * FF];
        const float* p1 = g_feat1 + (size_t)(2 * s) * RPA1 * FF + lane;
#pragma unroll 5
        for (int i = 0; i < RPA1; i++) a10 += p1[(size_t)i * FF];
#pragma unroll 5
        for (int i = 0; i < RPA1; i++) a11 += p1[(size_t)(RPA1 + i) * FF];
    }

    // ---- meta gate ----
    const float v0 = a00 + a01;
    const float v1 = a10 + a11;
    float l[NEXP];
#pragma unroll
    for (int e = 0; e < NEXP; e++) {
        float p = v0 * mw[lane * NEXP + e] + v1 * mw[(FF + lane) * NEXP + e];
#pragma unroll
        for (int o = 16; o > 0; o >>= 1) p += __shfl_xor_sync(0xffffffffu, p, o);
        l[e] = p + mb[e];
    }

    // ---- experts ----
    const float ngs_b2v = ngs_b2[0], tgs_b2v = tgs_b2[0], hyb_b2v = hyb_b2[0];
    const float ln0 = mlp32(a00, ngs_w1, ngs_b1, ngs_w2, ngs_b2v, lane);
    const float ln1 = mlp32(a01, ngs_w1, ngs_b1, ngs_w2, ngs_b2v, lane);
    const float lt0 = mlp32(a10, tgs_w1, tgs_b1, tgs_w2, tgs_b2v, lane);
    const float lt1 = mlp32(a11, tgs_w1, tgs_b1, tgs_w2, tgs_b2v, lane);
    const float lh0 = mlp64(a00, a10, hyb_w1, hyb_b1, hyb_w2, hyb_b2v, lane);
    const float lh1 = mlp64(a01, a11, hyb_w1, hyb_b1, hyb_w2, hyb_b2v, lane);

    if (lane == 0) {
        float pe[3][2] = {{ln0, ln1}, {lt0, lt1}, {lh0, lh1}};
#pragma unroll
        for (int e = 0; e < 3; e++) {
            const float m  = fmaxf(pe[e][0], pe[e][1]);
            const float z0 = expf(pe[e][0] - m);
            const float z1 = expf(pe[e][1] - m);
            const float inv = 1.0f / (z0 + z1);
            out[e * A_ALLELES + 2 * s]     = z0 * inv;
            out[e * A_ALLELES + 2 * s + 1] = z1 * inv;
        }
        const float m = fmaxf(l[0], fmaxf(l[1], l[2]));
        const float z0 = expf(l[0] - m), z1 = expf(l[1] - m), z2 = expf(l[2] - m);
        const float inv = 1.0f / (z0 + z1 + z2);
        out[3 * A_ALLELES + s * NEXP + 0] = z0 * inv;
        out[3 * A_ALLELES + s * NEXP + 1] = z1 * inv;
        out[3 * A_ALLELES + s * NEXP + 2] = z2 * inv;
    }
}

// ============================================================
// launch
// ============================================================
extern "C" void kernel_launch(void* const* d_in, const int* in_sizes, int n_in,
                              void* d_out, int out_size)
{
    const float* tensors0 = (const float*)d_in[0];
    const float* tensors1 = (const float*)d_in[1];
    const float* conv0_w  = (const float*)d_in[2];
    const float* conv0_b  = (const float*)d_in[3];
    const float* conv1_w  = (const float*)d_in[4];
    const float* conv1_b  = (const float*)d_in[5];
    const float* meta_w   = (const float*)d_in[6];
    const float* meta_b   = (const float*)d_in[7];
    const float* ngs_w1   = (const float*)d_in[8];
    const float* ngs_b1   = (const float*)d_in[9];
    const float* ngs_w2   = (const float*)d_in[10];
    const float* ngs_b2   = (const float*)d_in[11];
    const float* tgs_w1   = (const float*)d_in[12];
    const float* tgs_b1   = (const float*)d_in[13];
    const float* tgs_w2   = (const float*)d_in[14];
    const float* tgs_b2   = (const float*)d_in[15];
    const float* hyb_w1   = (const float*)d_in[16];
    const float* hyb_b1   = (const float*)d_in[17];
    const float* hyb_w2   = (const float*)d_in[18];
    const float* hyb_b2   = (const float*)d_in[19];

    float* out = (float*)d_out;

    const int R0 = in_sizes[0] / (CIN * LEN);
    const int R1 = in_sizes[1] / (CIN * LEN);
    const int T0 = R0 / RPB;
    const int T  = T0 + R1 / RPB;

    const int GRID  = 296;                       // 2 blocks per SM
    const int chunk = (T + GRID - 1) / GRID;

    conv_persist_kernel<<<GRID, 256>>>(tensors0, conv0_w, conv0_b,
                                       tensors1, conv1_w, conv1_b,
                                       T0, T, chunk);

    tail_kernel<<<(S_SITES + 7) / 8, 256>>>(
        meta_w, meta_b,
        ngs_w1, ngs_b1, ngs_w2, ngs_b2,
        tgs_w1, tgs_b1, tgs_w2, tgs_b2,
        hyb_w1, hyb_b1, hyb_w2, hyb_b2,
        out);
}

// round 8
// speedup vs baseline: 1.2640x; 1.1601x over previous
#include <cuda_runtime.h>
#include <cstdint>

// ---------------- fixed problem dims ----------------
#define S_SITES   1024
#define APS       2
#define A_ALLELES (S_SITES * APS)      // 2048
#define RPA0      20
#define RPA1      10
#define R0_MAX    (A_ALLELES * RPA0)   // 40960
#define R1_MAX    (A_ALLELES * RPA1)   // 20480
#define CIN       10
#define LEN       100
#define FF        32
#define KK        5
#define HH        64
#define NEXP      3
#define LOUT      96
#define WCOUNT    (CIN * KK)            // 50

// ---------------- scratch ----------------
__device__ float g_feat0[R0_MAX * FF];
__device__ float g_feat1[R1_MAX * FF];

// ============================================================
// Stage A: persistent tf32 tensor-core conv, cp.async pipeline,
// B in registers, software-pipelined A-fragment loads, 2 blocks/SM.
// ============================================================
#define RPB    4
#define SROW   104

__device__ __forceinline__ uint32_t f2tf32(float f) {
    uint32_t r;
    asm("cvt.rna.tf32.f32 %0, %1;" : "=r"(r) : "f"(f));
    return r;
}

__device__ __forceinline__ void mma_tf32(float acc[4],
                                         uint32_t a0, uint32_t a1, uint32_t a2, uint32_t a3,
                                         uint32_t b0, uint32_t b1) {
    asm volatile(
        "mma.sync.aligned.m16n8k8.row.col.f32.tf32.tf32.f32 "
        "{%0,%1,%2,%3}, {%4,%5,%6,%7}, {%8,%9}, {%0,%1,%2,%3};"
        : "+f"(acc[0]), "+f"(acc[1]), "+f"(acc[2]), "+f"(acc[3])
        : "r"(a0), "r"(a1), "r"(a2), "r"(a3), "r"(b0), "r"(b1));
}

__device__ __forceinline__ void cp_async16(void* smem, const void* gmem) {
    uint32_t s = (uint32_t)__cvta_generic_to_shared(smem);
    asm volatile("cp.async.cg.shared.global [%0], [%1], 16;" :: "r"(s), "l"(gmem));
}
#define CP_COMMIT()   asm volatile("cp.async.commit_group;")
#define CP_WAIT(N)    asm volatile("cp.async.wait_group %0;" :: "n"(N))

__global__ __launch_bounds__(256, 2)
void conv_persist_kernel(const float* __restrict__ x0,
                         const float* __restrict__ w0,
                         const float* __restrict__ b0,
                         const float* __restrict__ x1,
                         const float* __restrict__ w1,
                         const float* __restrict__ b1,
                         int T0, int T, int chunk)
{
    __shared__ float sx[2][RPB][CIN * SROW];   // 33280 B
    __shared__ float sb[2][FF];                //   256 B
    __shared__ float sred[RPB][2][FF];         //  1024 B

    const int tid  = threadIdx.x;
    const int warp = tid >> 5;
    const int lane = tid & 31;
    const int li   = lane & 3;
    const int lg   = lane >> 2;

    if (tid < 2 * FF) {
        const int tech = tid >> 5;
        const int f    = tid & 31;
        sb[tech][f] = tech ? b1[f] : b0[f];
    }

    const int tbeg = blockIdx.x * chunk;
    if (tbeg >= T) return;
    const int n = min(chunk, T - tbeg);

    // ---- im2col offsets per kt (two halves of the k8 tile) ----
    int offA[7], offB[7];
#pragma unroll
    for (int kt = 0; kt < 7; kt++) {
        const int kk0 = kt * 8 + li;
        const int kk1 = kk0 + 4;
        const int ka0 = (kk0 < WCOUNT) ? kk0 : (WCOUNT - 1);
        const int ka1 = (kk1 < WCOUNT) ? kk1 : (WCOUNT - 1);
        offA[kt] = (ka0 / KK) * SROW + (ka0 % KK);
        offB[kt] = (ka1 / KK) * SROW + (ka1 % KK);
    }

    // ---- prefetch pads (hoisted divisions) ----
    int ppad[4];
#pragma unroll
    for (int j = 0; j < 4; j++) {
        const int idx = tid + j * 256;
        const int r   = idx / 250;
        const int rem = idx - r * 250;
        const int c   = rem / 25;
        ppad[j] = r * 40 + c * 4;
    }

    auto prefetch = [&](int t, int st) {
        const bool is0 = (t < T0);
        const float* xx = is0 ? x0 : x1;
        const int rbase = is0 ? t * RPB : (t - T0) * RPB;
        const float* gp = xx + (size_t)rbase * (CIN * LEN);
        float* sp = &sx[st][0][0];
#pragma unroll
        for (int j = 0; j < 4; j++) {
            const int idx = tid + j * 256;
            if (idx < RPB * 250)
                cp_async16(sp + idx * 4 + ppad[j], gp + idx * 4);
        }
    };

    uint32_t B[7][4][2];
    int curtech = -1;

    // ---- prologue ----
    prefetch(tbeg, 0); CP_COMMIT();
    if (n > 1) { prefetch(tbeg + 1, 1); CP_COMMIT(); CP_WAIT(1); }
    else       { CP_WAIT(0); }
    __syncthreads();

    const int rloc = warp >> 1;
    const int half = warp & 1;
    const int rowb = half * 48 + lg;

    for (int it = 0; it < n; it++) {
        const int t    = tbeg + it;
        const int st   = it & 1;
        const bool is0 = (t < T0);
        const int tech = is0 ? 0 : 1;

        if (tech != curtech) {
            curtech = tech;
            const float* w = is0 ? w0 : w1;
#pragma unroll
            for (int kt = 0; kt < 7; kt++) {
                const int kk0 = kt * 8 + li;
                const int kk1 = kk0 + 4;
#pragma unroll
                for (int nt = 0; nt < 4; nt++) {
                    const int f = nt * 8 + lg;
                    B[kt][nt][0] = (kk0 < WCOUNT) ? f2tf32(w[f * WCOUNT + kk0]) : 0u;
                    B[kt][nt][1] = (kk1 < WCOUNT) ? f2tf32(w[f * WCOUNT + kk1]) : 0u;
                }
            }
        }

        const float* __restrict__ sr = sx[st][rloc];

        float acc[3][4][4];
#pragma unroll
        for (int mt = 0; mt < 3; mt++)
#pragma unroll
            for (int nt = 0; nt < 4; nt++)
#pragma unroll
                for (int j = 0; j < 4; j++) acc[mt][nt][j] = 0.0f;

        // ---- software-pipelined (kt, mt) stages with rotate ----
        uint32_t c0, c1, c2, c3;      // current A fragment
        c0 = __float_as_uint(sr[offA[0] + rowb]);
        c1 = __float_as_uint(sr[offA[0] + rowb + 8]);
        c2 = __float_as_uint(sr[offB[0] + rowb]);
        c3 = __float_as_uint(sr[offB[0] + rowb + 8]);

#pragma unroll
        for (int kt = 0; kt < 7; kt++) {
#pragma unroll
            for (int mt = 0; mt < 3; mt++) {
                uint32_t n0 = 0, n1 = 0, n2 = 0, n3 = 0;
                const bool last = (kt == 6) && (mt == 2);
                if (!last) {
                    const int nkt = (mt == 2) ? kt + 1 : kt;
                    const int nmt = (mt == 2) ? 0 : mt + 1;
                    const int row = rowb + nmt * 16;
                    n0 = __float_as_uint(sr[offA[nkt] + row]);
                    n1 = __float_as_uint(sr[offA[nkt] + row + 8]);
                    n2 = __float_as_uint(sr[offB[nkt] + row]);
                    n3 = __float_as_uint(sr[offB[nkt] + row + 8]);
                }

#pragma unroll
                for (int nt = 0; nt < 4; nt++)
                    mma_tf32(acc[mt][nt], c0, c1, c2, c3, B[kt][nt][0], B[kt][nt][1]);

                c0 = n0; c1 = n1; c2 = n2; c3 = n3;
            }
        }

        // ---- epilogue: bias + relu + row-sum, lane reduce ----
#pragma unroll
        for (int nt = 0; nt < 4; nt++) {
            const float bbl0 = sb[tech][nt * 8 + 2 * li + 0];
            const float bbl1 = sb[tech][nt * 8 + 2 * li + 1];
            float s0 = 0.0f, s1 = 0.0f;
#pragma unroll
            for (int mt = 0; mt < 3; mt++) {
                s0 += fmaxf(acc[mt][nt][0] + bbl0, 0.0f);
                s0 += fmaxf(acc[mt][nt][2] + bbl0, 0.0f);
                s1 += fmaxf(acc[mt][nt][1] + bbl1, 0.0f);
                s1 += fmaxf(acc[mt][nt][3] + bbl1, 0.0f);
            }
#pragma unroll
            for (int o = 16; o >= 4; o >>= 1) {
                s0 += __shfl_down_sync(0xffffffffu, s0, o);
                s1 += __shfl_down_sync(0xffffffffu, s1, o);
            }
            if (lane < 4) {
                sred[rloc][half][nt * 8 + 2 * lane + 0] = s0;
                sred[rloc][half][nt * 8 + 2 * lane + 1] = s1;
            }
        }

        __syncthreads();   // sred complete; sx[st] free

        if (tid < RPB * FF) {
            const int r = tid >> 5;
            const int f = tid & 31;
            const int rbase = is0 ? t * RPB : (t - T0) * RPB;
            float* feat = is0 ? g_feat0 : g_feat1;
            feat[(size_t)(rbase + r) * FF + f] =
                (sred[r][0][f] + sred[r][1][f]) * (1.0f / (float)LOUT);
        }

        if (it + 2 < n) {
            prefetch(tbeg + it + 2, st);
            CP_COMMIT();
            CP_WAIT(1);
        } else {
            CP_WAIT(0);
        }
        __syncthreads();
    }
}

// ============================================================
// Fused tail: warp per site.
// ============================================================
__device__ __forceinline__ float mlp32(float in, const float* __restrict__ w1,
                                       const float* __restrict__ b1,
                                       const float* __restrict__ w2, float b2,
                                       int lane)
{
    float h0 = b1[lane], h1 = b1[lane + 32];
#pragma unroll
    for (int f = 0; f < FF; f++) {
        const float v = __shfl_sync(0xffffffffu, in, f);
        h0 = fmaf(v, w1[f * HH + lane], h0);
        h1 = fmaf(v, w1[f * HH + lane + 32], h1);
    }
    float p = fmaxf(h0, 0.0f) * w2[lane] + fmaxf(h1, 0.0f) * w2[lane + 32];
#pragma unroll
    for (int o = 16; o > 0; o >>= 1) p += __shfl_xor_sync(0xffffffffu, p, o);
    return p + b2;
}

__device__ __forceinline__ float mlp64(float in0, float in1,
                                       const float* __restrict__ w1,
                                       const float* __restrict__ b1,
                                       const float* __restrict__ w2, float b2,
                                       int lane)
{
    float h0 = b1[lane], h1 = b1[lane + 32];
#pragma unroll
    for (int f = 0; f < FF; f++) {
        const float v0 = __shfl_sync(0xffffffffu, in0, f);
        const float v1 = __shfl_sync(0xffffffffu, in1, f);
        h0 = fmaf(v0, w1[f * HH + lane], h0);
        h1 = fmaf(v0, w1[f * HH + lane + 32], h1);
        h0 = fmaf(v1, w1[(FF + f) * HH + lane], h0);
        h1 = fmaf(v1, w1[(FF + f) * HH + lane + 32], h1);
    }
    float p = fmaxf(h0, 0.0f) * w2[lane] + fmaxf(h1, 0.0f) * w2[lane + 32];
#pragma unroll
    for (int o = 16; o > 0; o >>= 1) p += __shfl_xor_sync(0xffffffffu, p, o);
    return p + b2;
}

__global__ __launch_bounds__(256)
void tail_kernel(const float* __restrict__ mw,   const float* __restrict__ mb,
                 const float* __restrict__ ngs_w1, const float* __restrict__ ngs_b1,
                 const float* __restrict__ ngs_w2, const float* __restrict__ ngs_b2,
                 const float* __restrict__ tgs_w1, const float* __restrict__ tgs_b1,
                 const float* __restrict__ tgs_w2, const float* __restrict__ tgs_b2,
                 const float* __restrict__ hyb_w1, const float* __restrict__ hyb_b1,
                 const float* __restrict__ hyb_w2, const float* __restrict__ hyb_b2,
                 float* __restrict__ out)
{
    const int warp = threadIdx.x >> 5;
    const int lane = threadIdx.x & 31;
    const int s = blockIdx.x * (blockDim.x >> 5) + warp;
    if (s >= S_SITES) return;

    float a00 = 0.0f, a01 = 0.0f, a10 = 0.0f, a11 = 0.0f;
    {
        const float* p0 = g_feat0 + (size_t)(2 * s) * RPA0 * FF + lane;
#pragma unroll 4
        for (int i = 0; i < RPA0; i++) a00 += p0[(size_t)i * FF];
#pragma unroll 4
        for (int i = 0; i < RPA0; i++) a01 += p0[(size_t)(RPA0 + i) * FF];
        const float* p1 = g_feat1 + (size_t)(2 * s) * RPA1 * FF + lane;
#pragma unroll 5
        for (int i = 0; i < RPA1; i++) a10 += p1[(size_t)i * FF];
#pragma unroll 5
        for (int i = 0; i < RPA1; i++) a11 += p1[(size_t)(RPA1 + i) * FF];
    }

    const float v0 = a00 + a01;
    const float v1 = a10 + a11;
    float l[NEXP];
#pragma unroll
    for (int e = 0; e < NEXP; e++) {
        float p = v0 * mw[lane * NEXP + e] + v1 * mw[(FF + lane) * NEXP + e];
#pragma unroll
        for (int o = 16; o > 0; o >>= 1) p += __shfl_xor_sync(0xffffffffu, p, o);
        l[e] = p + mb[e];
    }

    const float ngs_b2v = ngs_b2[0], tgs_b2v = tgs_b2[0], hyb_b2v = hyb_b2[0];
    const float ln0 = mlp32(a00, ngs_w1, ngs_b1, ngs_w2, ngs_b2v, lane);
    const float ln1 = mlp32(a01, ngs_w1, ngs_b1, ngs_w2, ngs_b2v, lane);
    const float lt0 = mlp32(a10, tgs_w1, tgs_b1, tgs_w2, tgs_b2v, lane);
    const float lt1 = mlp32(a11, tgs_w1, tgs_b1, tgs_w2, tgs_b2v, lane);
    const float lh0 = mlp64(a00, a10, hyb_w1, hyb_b1, hyb_w2, hyb_b2v, lane);
    const float lh1 = mlp64(a01, a11, hyb_w1, hyb_b1, hyb_w2, hyb_b2v, lane);

    if (lane == 0) {
        float pe[3][2] = {{ln0, ln1}, {lt0, lt1}, {lh0, lh1}};
#pragma unroll
        for (int e = 0; e < 3; e++) {
            const float m  = fmaxf(pe[e][0], pe[e][1]);
            const float z0 = expf(pe[e][0] - m);
            const float z1 = expf(pe[e][1] - m);
            const float inv = 1.0f / (z0 + z1);
            out[e * A_ALLELES + 2 * s]     = z0 * inv;
            out[e * A_ALLELES + 2 * s + 1] = z1 * inv;
        }
        const float m = fmaxf(l[0], fmaxf(l[1], l[2]));
        const float z0 = expf(l[0] - m), z1 = expf(l[1] - m), z2 = expf(l[2] - m);
        const float inv = 1.0f / (z0 + z1 + z2);
        out[3 * A_ALLELES + s * NEXP + 0] = z0 * inv;
        out[3 * A_ALLELES + s * NEXP + 1] = z1 * inv;
        out[3 * A_ALLELES + s * NEXP + 2] = z2 * inv;
    }
}

// ============================================================
// launch
// ============================================================
extern "C" void kernel_launch(void* const* d_in, const int* in_sizes, int n_in,
                              void* d_out, int out_size)
{
    const float* tensors0 = (const float*)d_in[0];
    const float* tensors1 = (const float*)d_in[1];
    const float* conv0_w  = (const float*)d_in[2];
    const float* conv0_b  = (const float*)d_in[3];
    const float* conv1_w  = (const float*)d_in[4];
    const float* conv1_b  = (const float*)d_in[5];
    const float* meta_w   = (const float*)d_in[6];
    const float* meta_b   = (const float*)d_in[7];
    const float* ngs_w1   = (const float*)d_in[8];
    const float* ngs_b1   = (const float*)d_in[9];
    const float* ngs_w2   = (const float*)d_in[10];
    const float* ngs_b2   = (const float*)d_in[11];
    const float* tgs_w1   = (const float*)d_in[12];
    const float* tgs_b1   = (const float*)d_in[13];
    const float* tgs_w2   = (const float*)d_in[14];
    const float* tgs_b2   = (const float*)d_in[15];
    const float* hyb_w1   = (const float*)d_in[16];
    const float* hyb_b1   = (const float*)d_in[17];
    const float* hyb_w2   = (const float*)d_in[18];
    const float* hyb_b2   = (const float*)d_in[19];

    float* out = (float*)d_out;

    const int R0 = in_sizes[0] / (CIN * LEN);
    const int R1 = in_sizes[1] / (CIN * LEN);
    const int T0 = R0 / RPB;
    const int T  = T0 + R1 / RPB;

    const int GRID  = 296;                       // 2 blocks per SM
    const int chunk = (T + GRID - 1) / GRID;

    conv_persist_kernel<<<GRID, 256>>>(tensors0, conv0_w, conv0_b,
                                       tensors1, conv1_w, conv1_b,
                                       T0, T, chunk);

    tail_kernel<<<(S_SITES + 7) / 8, 256>>>(
        meta_w, meta_b,
        ngs_w1, ngs_b1, ngs_w2, ngs_b2,
        tgs_w1, tgs_b1, tgs_w2, tgs_b2,
        hyb_w1, hyb_b1, hyb_w2, hyb_b2,
        out);
}